// round 11
// baseline (speedup 1.0000x reference)
#include <cuda_runtime.h>
#include <cstdint>

// Problem constants (B=2, T=2048, C=1024, H=16, hd=64, MLP width 32)
#define BSZ   2
#define TSEQ  2048
#define CDIM  1024
#define NH    16
#define HD    64
#define MLPW  32
#define UPAD  64
#define LOG2E 1.4426950408889634f

__device__ float g_qkv[3 * BSZ * NH * TSEQ * HD];
__device__ float g_y[BSZ * TSEQ * CDIM];
__device__ float g_ut2[TSEQ + UPAD];  // log(|c*max(i-UPAD,0)|+1)
__device__ float g_invP[TSEQ];        // 1/(log(|c*max(t,thr)|+1)+eps)

// ===========================================================================
// Helpers
// ===========================================================================
__device__ __forceinline__ uint32_t smem_u32(const void* p) {
    uint32_t a;
    asm("{ .reg .u64 t; cvta.to.shared.u64 t, %1; cvt.u32.u64 %0, t; }"
        : "=r"(a) : "l"(p));
    return a;
}
#define CP_ASYNC16(dst, src) \
    asm volatile("cp.async.cg.shared.global [%0], [%1], 16;" \
                 :: "r"(dst), "l"(src) : "memory")
#define CP_COMMIT() asm volatile("cp.async.commit_group;" ::: "memory")
#define CP_WAIT(n)  asm volatile("cp.async.wait_group %0;" :: "n"(n) : "memory")

__device__ __forceinline__ uint32_t f2tf32(float f) {
    uint32_t r;
    asm("cvt.rna.tf32.f32 %0, %1;" : "=r"(r) : "f"(f));
    return r;
}
__device__ __forceinline__ float rnaf(float f) {
    return __uint_as_float(f2tf32(f));
}
__device__ __forceinline__ float ex2(float x) {
    float y;
    asm("ex2.approx.f32 %0, %1;" : "=f"(y) : "f"(x));
    return y;
}
__device__ __forceinline__ void mma8(float* c, const uint32_t* a,
                                     const uint32_t* b) {
    asm volatile(
        "mma.sync.aligned.m16n8k8.row.col.f32.tf32.tf32.f32 "
        "{%0,%1,%2,%3}, {%4,%5,%6,%7}, {%8,%9}, {%0,%1,%2,%3};"
        : "+f"(c[0]), "+f"(c[1]), "+f"(c[2]), "+f"(c[3])
        : "r"(a[0]), "r"(a[1]), "r"(a[2]), "r"(a[3]), "r"(b[0]), "r"(b[1]));
}
__device__ __forceinline__ void ldm_x4(uint32_t& r0, uint32_t& r1,
                                       uint32_t& r2, uint32_t& r3,
                                       uint32_t addr) {
    asm volatile(
        "ldmatrix.sync.aligned.m8n8.x4.shared.b16 {%0,%1,%2,%3}, [%4];"
        : "=r"(r0), "=r"(r1), "=r"(r2), "=r"(r3) : "r"(addr));
}

// ===========================================================================
// Init: FIRE log tables
// ===========================================================================
__global__ void init_tables(const float* __restrict__ cp,
                            const float* __restrict__ lm) {
    const int i = blockIdx.x * blockDim.x + threadIdx.x;
    if (i >= TSEQ + UPAD) return;
    const float c = cp[0];
    const int   rel = i - UPAD;
    g_ut2[i] = logf(fabsf(c * (float)(rel < 0 ? 0 : rel)) + 1.0f);
    if (i < TSEQ) {
        const float thr = fabsf(lm[0] * 512.0f);
        g_invP[i] =
            1.0f / (logf(fabsf(c * fmaxf((float)i, thr)) + 1.0f) + 1e-6f);
    }
}

// ===========================================================================
// tf32 mma.sync GEMM, 4-stage cp.async pipeline (unchanged from R10 best).
// ===========================================================================
#define ABUF (128 * 20 * 4)
#define BBUF (16 * 136 * 4)
#define NSTG 4
#define GSMEM (NSTG * (ABUF + BBUF))

template <int MODE>
__global__ __launch_bounds__(256, 2) void mma_gemm(const float* __restrict__ A,
                                                   const float* __restrict__ Bm,
                                                   const float* __restrict__ bias,
                                                   float* __restrict__ out,
                                                   int K, int N) {
    extern __shared__ char sm[];
    const uint32_t sbase = smem_u32(sm);

    const int tid   = threadIdx.x;
    const int lane  = tid & 31;
    const int wid   = tid >> 5;
    const int warpM = wid & 3;
    const int warpN = wid >> 2;
    const int m0    = blockIdx.y * 128;
    const int n0    = blockIdx.x * 128;

    const int ar = tid >> 2;
    const int ak = (tid & 3) * 4;
    const float* Ag = A + (size_t)(m0 + ar) * K + ak;
    const int br = tid >> 4;
    const int bc = (tid & 15) * 4;
    const float* Bg = Bm + (size_t)br * N + n0 + bc;

    const uint32_t aOff0 = (uint32_t)(ar * 20 + ak) * 4;
    const uint32_t aOff1 = (uint32_t)((ar + 64) * 20 + ak) * 4;
    const uint32_t bOff0 = (uint32_t)(br * 136 + bc) * 4;
    const uint32_t bOff1 = (uint32_t)(br * 136 + bc + 64) * 4;

#define LOADTILE(st, kc)                                                      \
    do {                                                                      \
        const uint32_t as = sbase + (st) * ABUF;                              \
        const uint32_t bs = sbase + NSTG * ABUF + (st) * BBUF;                \
        CP_ASYNC16(as + aOff0, Ag + (kc) * 16);                               \
        CP_ASYNC16(as + aOff1, Ag + (size_t)64 * K + (kc) * 16);              \
        CP_ASYNC16(bs + bOff0, Bg + (size_t)(kc) * 16 * N);                   \
        CP_ASYNC16(bs + bOff1, Bg + (size_t)(kc) * 16 * N + 64);              \
        CP_COMMIT();                                                          \
    } while (0)

    float acc[2][8][4];
#pragma unroll
    for (int mf = 0; mf < 2; mf++)
#pragma unroll
        for (int nf = 0; nf < 8; nf++)
#pragma unroll
            for (int i = 0; i < 4; i++) acc[mf][nf][i] = 0.0f;

    const int r  = lane >> 2;
    const int cq = lane & 3;
    const int nk = K >> 4;

    LOADTILE(0, 0);
    LOADTILE(1, 1);
    LOADTILE(2, 2);

#pragma unroll 1
    for (int it = 0; it < nk; it++) {
        const int st  = it & (NSTG - 1);
        const int rem = nk - 1 - it;
        if (rem >= 2)      CP_WAIT(2);
        else if (rem == 1) CP_WAIT(1);
        else               CP_WAIT(0);
        __syncthreads();

        const float* Asf = (const float*)(sm + st * ABUF);
        const float* Bsf = (const float*)(sm + NSTG * ABUF + st * BBUF);

#pragma unroll
        for (int ks = 0; ks < 2; ks++) {
            const int kb = ks * 8;
            uint32_t af[2][4];
#pragma unroll
            for (int mf = 0; mf < 2; mf++) {
                const int mrow = warpM * 32 + mf * 16 + r;
                af[mf][0] = f2tf32(Asf[mrow * 20 + kb + cq]);
                af[mf][1] = f2tf32(Asf[(mrow + 8) * 20 + kb + cq]);
                af[mf][2] = f2tf32(Asf[mrow * 20 + kb + cq + 4]);
                af[mf][3] = f2tf32(Asf[(mrow + 8) * 20 + kb + cq + 4]);
            }
#pragma unroll
            for (int nf = 0; nf < 8; nf++) {
                const int ncol = warpN * 64 + nf * 8 + r;
                uint32_t bfr[2];
                bfr[0] = f2tf32(Bsf[(kb + cq) * 136 + ncol]);
                bfr[1] = f2tf32(Bsf[(kb + cq + 4) * 136 + ncol]);
                mma8(acc[0][nf], af[0], bfr);
                mma8(acc[1][nf], af[1], bfr);
            }
        }

        if (it + 3 < nk) LOADTILE((it + 3) & (NSTG - 1), it + 3);
    }
#undef LOADTILE

#pragma unroll
    for (int mf = 0; mf < 2; mf++) {
#pragma unroll
        for (int nf = 0; nf < 8; nf++) {
            const int n = n0 + warpN * 64 + nf * 8 + 2 * cq;
            const float bx = bias[n], by = bias[n + 1];
#pragma unroll
            for (int half = 0; half < 2; half++) {
                const int m = m0 + warpM * 32 + mf * 16 + r + half * 8;
                float2 v = make_float2(acc[mf][nf][half * 2] + bx,
                                       acc[mf][nf][half * 2 + 1] + by);
                if (MODE == 0) {
                    const int which = n >> 10;
                    const int hh    = (n & 1023) >> 6;
                    const int d     = n & 63;
                    const int bb    = m >> 11;
                    const int t     = m & 2047;
                    *(float2*)&g_qkv[which * (BSZ * NH * TSEQ * HD) +
                                     ((bb * NH + hh) * TSEQ + t) * HD + d] = v;
                } else {
                    *(float2*)&out[(size_t)m * N + n] = v;
                }
            }
        }
    }
}

// ===========================================================================
// FA2-style flash attention. R11: Q lives in SMEM (tf32-pre-rounded,
// pitch 68 = conflict-free), A-frags via ldmatrix per tile-iter. This cuts
// ~32 registers so __launch_bounds__(256,2) fits WITHOUT spilling ->
// 2 CTAs/SM. Scores carry a folded log2e so exp = bare ex2.approx.
// Dynamic smem layout (floats):
//   Qs [128][68] @ 0, Ks [2][32][68] @ 8704, Vt [2][64][36] @ 13056,
//   weights @ 17664.
// ===========================================================================
#define QS_OFF 0
#define KS_OFF (128 * 68)
#define VT_OFF (KS_OFF + 2 * 32 * 68)
#define W_OFF  (VT_OFF + 2 * 64 * 36)
#define ASMEM  ((W_OFF + 104) * 4)

__device__ __forceinline__ float fire_mlp(float nd, const float* sw1,
                                          const float* sb1, const float* sw2) {
    float acc = 0.0f;
#pragma unroll
    for (int w = 0; w < MLPW; w++)
        acc = fmaf(fmaxf(fmaf(nd, sw1[w], sb1[w]), 0.0f), sw2[w], acc);
    return acc;
}

__global__ __launch_bounds__(256, 2) void attn_mma(
        const float* __restrict__ w1, const float* __restrict__ b1,
        const float* __restrict__ w2) {
    extern __shared__ float af_[];
    float* Qs  = af_ + QS_OFF;   // [q][68]
    float* Ksm = af_ + KS_OFF;   // [buf][key][68]
    float* Vtm = af_ + VT_OFF;   // [buf][d][36]
    float* sw1 = af_ + W_OFF;
    float* sb1 = sw1 + MLPW;
    float* sw2 = sb1 + MLPW;
    float* sA  = sw2 + MLPW;     // [0]=alpha, [1]=lin

    const int tid  = threadIdx.x;
    const int lane = tid & 31;
    const int warp = tid >> 5;
    const int h    = blockIdx.y;
    const int b    = blockIdx.z;
    const int q0   = (gridDim.x - 1 - blockIdx.x) * 128;
    const int tw   = q0 + warp * 16;
    const int r    = lane >> 2;
    const int cq   = lane & 3;
    const int t0   = tw + r;
    const int t1   = t0 + 8;

    if (tid < MLPW) {
        sw1[tid] = w1[tid];
        sb1[tid] = b1[tid];
        sw2[tid] = w2[tid * NH + h];
    }
    __syncthreads();
    if (tid == 0) {
        bool  lin = true;
        float a   = 0.0f;
#pragma unroll
        for (int w = 0; w < MLPW; w++) {
            lin = lin && (sb1[w] == 0.0f);
            a   = fmaf(fmaxf(sw1[w], 0.0f), sw2[w], a);
        }
        sA[0] = a;
        sA[1] = lin ? 1.0f : 0.0f;
    }

    const float invP0 = g_invP[t0];
    const float invP1 = g_invP[t1];

    const float* Qg = g_qkv + (size_t)(b * NH + h) * TSEQ * HD;
    const float* Kg = Qg + (size_t)BSZ * NH * TSEQ * HD;
    const float* Vg = Kg + (size_t)BSZ * NH * TSEQ * HD;

    // ---- stage Q tile (pre-scaled by log2e/sqrt(hd), tf32 rna) ----
    {
        const float qsc = 0.125f * LOG2E;
#pragma unroll
        for (int j = 0; j < 8; j++) {
            const int v   = tid + j * 256;   // 0..2047 float4 slots
            const int row = v >> 4;
            const int c4  = v & 15;
            float4 q4 = *(const float4*)&Qg[(size_t)(q0 + row) * HD + c4 * 4];
            *(float4*)&Qs[row * 68 + c4 * 4] =
                make_float4(rnaf(q4.x * qsc), rnaf(q4.y * qsc),
                            rnaf(q4.z * qsc), rnaf(q4.w * qsc));
        }
    }

    float o[8][4];
#pragma unroll
    for (int nd = 0; nd < 8; nd++)
#pragma unroll
        for (int i = 0; i < 4; i++) o[nd][i] = 0.0f;
    float m0 = -1e30f, m1 = -1e30f, l0 = 0.0f, l1 = 0.0f;

    const int krow = tid >> 3;
    const int kc   = tid & 7;
    float4 kreg0, kreg1;
    float  vreg[8];

    {   // prologue: K/V tile 0 into buf 0
        const float4* kp = (const float4*)&Kg[(size_t)krow * HD];
        kreg0 = kp[kc];
        kreg1 = kp[kc + 8];
#pragma unroll
        for (int i = 0; i < 8; i++)
            vreg[i] = Vg[(size_t)krow * HD + kc + 8 * i];
        *(float4*)&Ksm[krow * 68 + kc * 4] =
            make_float4(rnaf(kreg0.x), rnaf(kreg0.y), rnaf(kreg0.z), rnaf(kreg0.w));
        *(float4*)&Ksm[krow * 68 + kc * 4 + 32] =
            make_float4(rnaf(kreg1.x), rnaf(kreg1.y), rnaf(kreg1.z), rnaf(kreg1.w));
#pragma unroll
        for (int i = 0; i < 8; i++) Vtm[(kc + 8 * i) * 36 + krow] = rnaf(vreg[i]);
    }
    __syncthreads();

    const float alpha = sA[0];
    const int   lin   = (sA[1] != 0.0f);
    const float ai0   = alpha * invP0 * LOG2E;
    const float ai1   = alpha * invP1 * LOG2E;
    const float* ut   = g_ut2 + UPAD;

    // Q a-frag ldmatrix addressing (16 rows x 8 cols per x4)
    const uint32_t qb    = smem_u32(Qs);
    const uint32_t qrow  = (uint32_t)(warp * 16 + (lane & 7) + 8 * ((lane >> 3) & 1));
    const uint32_t qcoff = 4u * ((uint32_t)lane >> 4);
    const uint32_t qaddr0 = qb + 4u * (qrow * 68u + qcoff);

    const int nt = (q0 + 128) >> 5;
#pragma unroll 1
    for (int it = 0; it < nt; it++) {
        const int  buf = it & 1;
        const int  s0  = it * 32;
        const bool nxt = (it + 1) < nt;

        if (nxt) {
            const float4* kp = (const float4*)&Kg[(size_t)(s0 + 32 + krow) * HD];
            kreg0 = kp[kc];
            kreg1 = kp[kc + 8];
#pragma unroll
            for (int i = 0; i < 8; i++)
                vreg[i] = Vg[(size_t)(s0 + 32 + krow) * HD + kc + 8 * i];
        }

        if (s0 <= tw + 15) {
            const bool     msk = (s0 + 31) > tw;
            const uint32_t kb  = smem_u32(&Ksm[buf * 32 * 68]);
            const uint32_t vb  = smem_u32(&Vtm[buf * 64 * 36]);

            // ---- QK^T (Q frags from smem per kfp) ----
            float s[4][4];
#pragma unroll
            for (int nf = 0; nf < 4; nf++)
                s[nf][0] = s[nf][1] = s[nf][2] = s[nf][3] = 0.0f;
#pragma unroll
            for (int kfp = 0; kfp < 4; kfp++) {
                uint32_t qf0[4], qf1[4];
                ldm_x4(qf0[0], qf0[1], qf0[2], qf0[3], qaddr0 + 4u * (16u * kfp));
                ldm_x4(qf1[0], qf1[1], qf1[2], qf1[3], qaddr0 + 4u * (16u * kfp + 8u));
#pragma unroll
                for (int nf = 0; nf < 4; nf++) {
                    uint32_t bb[4];
                    const uint32_t addr = kb +
                        4u * ((uint32_t)(8 * nf + (lane & 7)) * 68u +
                              16u * kfp + 4u * (lane >> 3));
                    ldm_x4(bb[0], bb[1], bb[2], bb[3], addr);
                    mma8(s[nf], qf0, bb);
                    mma8(s[nf], qf1, bb + 2);
                }
            }

            // ---- bias (log2e units) + mask + tile max ----
            float mt0 = -1e30f, mt1 = -1e30f;
#pragma unroll
            for (int nf = 0; nf < 4; nf++) {
                const int k0    = s0 + nf * 8 + 2 * cq;
                const int rel00 = t0 - k0;
                const float u00 = __ldg(&ut[rel00]);
                const float u01 = __ldg(&ut[rel00 - 1]);
                const float u10 = __ldg(&ut[rel00 + 8]);
                const float u11 = __ldg(&ut[rel00 + 7]);
                if (lin) {
                    s[nf][0] = fmaf(ai0, u00, s[nf][0]);
                    s[nf][1] = fmaf(ai0, u01, s[nf][1]);
                    s[nf][2] = fmaf(ai1, u10, s[nf][2]);
                    s[nf][3] = fmaf(ai1, u11, s[nf][3]);
                } else {
                    s[nf][0] = fmaf(fire_mlp(u00 * invP0, sw1, sb1, sw2), LOG2E, s[nf][0]);
                    s[nf][1] = fmaf(fire_mlp(u01 * invP0, sw1, sb1, sw2), LOG2E, s[nf][1]);
                    s[nf][2] = fmaf(fire_mlp(u10 * invP1, sw1, sb1, sw2), LOG2E, s[nf][2]);
                    s[nf][3] = fmaf(fire_mlp(u11 * invP1, sw1, sb1, sw2), LOG2E, s[nf][3]);
                }
                if (msk) {
                    if (rel00 < 0)     s[nf][0] = -1e30f;
                    if (rel00 - 1 < 0) s[nf][1] = -1e30f;
                    if (rel00 + 8 < 0) s[nf][2] = -1e30f;
                    if (rel00 + 7 < 0) s[nf][3] = -1e30f;
                }
                mt0 = fmaxf(mt0, fmaxf(s[nf][0], s[nf][1]));
                mt1 = fmaxf(mt1, fmaxf(s[nf][2], s[nf][3]));
            }
            mt0 = fmaxf(mt0, __shfl_xor_sync(0xffffffffu, mt0, 1));
            mt0 = fmaxf(mt0, __shfl_xor_sync(0xffffffffu, mt0, 2));
            mt1 = fmaxf(mt1, __shfl_xor_sync(0xffffffffu, mt1, 1));
            mt1 = fmaxf(mt1, __shfl_xor_sync(0xffffffffu, mt1, 2));

            const float mn0 = fmaxf(m0, mt0);
            const float mn1 = fmaxf(m1, mt1);
            const float f0  = ex2(m0 - mn0);
            const float f1  = ex2(m1 - mn1);
            m0 = mn0; m1 = mn1;
            l0 *= f0;  l1 *= f1;
#pragma unroll
            for (int nd = 0; nd < 8; nd++) {
                o[nd][0] *= f0; o[nd][1] *= f0;
                o[nd][2] *= f1; o[nd][3] *= f1;
            }
#pragma unroll
            for (int nf = 0; nf < 4; nf++) {
                s[nf][0] = ex2(s[nf][0] - m0);
                s[nf][1] = ex2(s[nf][1] - m0);
                s[nf][2] = ex2(s[nf][2] - m1);
                s[nf][3] = ex2(s[nf][3] - m1);
                l0 += s[nf][0] + s[nf][1];
                l1 += s[nf][2] + s[nf][3];
            }

            // ---- PV ----
            const int src1 = (lane & 28) | (cq >> 1);
            const int src2 = src1 + 2;
#pragma unroll
            for (int kf2 = 0; kf2 < 4; kf2++) {
                const float x0 = __shfl_sync(0xffffffffu, s[kf2][0], src1);
                const float x1 = __shfl_sync(0xffffffffu, s[kf2][1], src1);
                const float y0 = __shfl_sync(0xffffffffu, s[kf2][0], src2);
                const float y1 = __shfl_sync(0xffffffffu, s[kf2][1], src2);
                const float x2 = __shfl_sync(0xffffffffu, s[kf2][2], src1);
                const float x3 = __shfl_sync(0xffffffffu, s[kf2][3], src1);
                const float y2 = __shfl_sync(0xffffffffu, s[kf2][2], src2);
                const float y3 = __shfl_sync(0xffffffffu, s[kf2][3], src2);
                uint32_t pa[4];
                pa[0] = f2tf32((cq & 1) ? x1 : x0);
                pa[1] = f2tf32((cq & 1) ? x3 : x2);
                pa[2] = f2tf32((cq & 1) ? y1 : y0);
                pa[3] = f2tf32((cq & 1) ? y3 : y2);
#pragma unroll
                for (int g = 0; g < 4; g++) {
                    uint32_t bv[4];
                    const uint32_t addr = vb +
                        4u * ((uint32_t)(8 * (2 * g + (lane >> 4)) + (lane & 7)) * 36u +
                              8u * kf2 + 4u * ((lane >> 3) & 1));
                    ldm_x4(bv[0], bv[1], bv[2], bv[3], addr);
                    mma8(o[2 * g], pa, bv);
                    mma8(o[2 * g + 1], pa, bv + 2);
                }
            }
        }

        if (nxt) {
            const int nb = buf ^ 1;
            *(float4*)&Ksm[nb * 32 * 68 + krow * 68 + kc * 4] =
                make_float4(rnaf(kreg0.x), rnaf(kreg0.y), rnaf(kreg0.z), rnaf(kreg0.w));
            *(float4*)&Ksm[nb * 32 * 68 + krow * 68 + kc * 4 + 32] =
                make_float4(rnaf(kreg1.x), rnaf(kreg1.y), rnaf(kreg1.z), rnaf(kreg1.w));
#pragma unroll
            for (int i = 0; i < 8; i++)
                Vtm[nb * 64 * 36 + (kc + 8 * i) * 36 + krow] = rnaf(vreg[i]);
        }
        __syncthreads();
    }

    l0 += __shfl_xor_sync(0xffffffffu, l0, 1);
    l0 += __shfl_xor_sync(0xffffffffu, l0, 2);
    l1 += __shfl_xor_sync(0xffffffffu, l1, 1);
    l1 += __shfl_xor_sync(0xffffffffu, l1, 2);
    const float inv0 = 1.0f / l0;
    const float inv1 = 1.0f / l1;
    float* y0p = &g_y[((size_t)(b * TSEQ) + t0) * CDIM + h * HD];
    float* y1p = &g_y[((size_t)(b * TSEQ) + t1) * CDIM + h * HD];
#pragma unroll
    for (int nd = 0; nd < 8; nd++) {
        const int d = nd * 8 + 2 * cq;
        *(float2*)&y0p[d] = make_float2(o[nd][0] * inv0, o[nd][1] * inv0);
        *(float2*)&y1p[d] = make_float2(o[nd][2] * inv1, o[nd][3] * inv1);
    }
}

// ===========================================================================
// Launch
// ===========================================================================
extern "C" void kernel_launch(void* const* d_in, const int* in_sizes, int n_in,
                              void* d_out, int out_size) {
    const float* x     = (const float*)d_in[0];
    const float* Wqkv  = (const float*)d_in[1];
    const float* bqkv  = (const float*)d_in[2];
    const float* Wproj = (const float*)d_in[3];
    const float* bproj = (const float*)d_in[4];
    const float* w1    = (const float*)d_in[5];
    const float* b1    = (const float*)d_in[6];
    const float* w2    = (const float*)d_in[7];
    const float* cpar  = (const float*)d_in[9];
    const float* lmul  = (const float*)d_in[10];
    float* out = (float*)d_out;

    cudaFuncSetAttribute(mma_gemm<0>,
                         cudaFuncAttributeMaxDynamicSharedMemorySize, GSMEM);
    cudaFuncSetAttribute(mma_gemm<1>,
                         cudaFuncAttributeMaxDynamicSharedMemorySize, GSMEM);
    cudaFuncSetAttribute(attn_mma,
                         cudaFuncAttributeMaxDynamicSharedMemorySize, ASMEM);

    init_tables<<<(TSEQ + UPAD + 255) / 256, 256>>>(cpar, lmul);

    mma_gemm<0><<<dim3(3 * CDIM / 128, BSZ * TSEQ / 128), 256, GSMEM>>>(
        x, Wqkv, bqkv, nullptr, CDIM, 3 * CDIM);

    attn_mma<<<dim3(TSEQ / 128, NH, BSZ), 256, ASMEM>>>(w1, b1, w2);

    float* gy_ptr = nullptr;
    cudaGetSymbolAddress((void**)&gy_ptr, g_y);
    mma_gemm<1><<<dim3(CDIM / 128, BSZ * TSEQ / 128), 256, GSMEM>>>(
        gy_ptr, Wproj, bproj, out, CDIM, CDIM);
}

// round 12
// speedup vs baseline: 1.2316x; 1.2316x over previous
#include <cuda_runtime.h>
#include <cstdint>

// Problem constants (B=2, T=2048, C=1024, H=16, hd=64, MLP width 32)
#define BSZ   2
#define TSEQ  2048
#define CDIM  1024
#define NH    16
#define HD    64
#define MLPW  32
#define UPAD  64
#define LOG2E 1.4426950408889634f

__device__ float g_qkv[3 * BSZ * NH * TSEQ * HD];
__device__ float g_y[BSZ * TSEQ * CDIM];
__device__ float g_ut2[TSEQ + UPAD];  // log(|c*max(i-UPAD,0)|+1)
__device__ float g_invP[TSEQ];        // 1/(log(|c*max(t,thr)|+1)+eps)

// ===========================================================================
// Helpers
// ===========================================================================
__device__ __forceinline__ uint32_t smem_u32(const void* p) {
    uint32_t a;
    asm("{ .reg .u64 t; cvta.to.shared.u64 t, %1; cvt.u32.u64 %0, t; }"
        : "=r"(a) : "l"(p));
    return a;
}
#define CP_ASYNC16(dst, src) \
    asm volatile("cp.async.cg.shared.global [%0], [%1], 16;" \
                 :: "r"(dst), "l"(src) : "memory")
#define CP_COMMIT() asm volatile("cp.async.commit_group;" ::: "memory")
#define CP_WAIT(n)  asm volatile("cp.async.wait_group %0;" :: "n"(n) : "memory")

__device__ __forceinline__ uint32_t f2tf32(float f) {
    uint32_t r;
    asm("cvt.rna.tf32.f32 %0, %1;" : "=r"(r) : "f"(f));
    return r;
}
__device__ __forceinline__ float rnaf(float f) {
    return __uint_as_float(f2tf32(f));
}
__device__ __forceinline__ float ex2(float x) {
    float y;
    asm("ex2.approx.f32 %0, %1;" : "=f"(y) : "f"(x));
    return y;
}
__device__ __forceinline__ void mma8(float* c, const uint32_t* a,
                                     const uint32_t* b) {
    asm volatile(
        "mma.sync.aligned.m16n8k8.row.col.f32.tf32.tf32.f32 "
        "{%0,%1,%2,%3}, {%4,%5,%6,%7}, {%8,%9}, {%0,%1,%2,%3};"
        : "+f"(c[0]), "+f"(c[1]), "+f"(c[2]), "+f"(c[3])
        : "r"(a[0]), "r"(a[1]), "r"(a[2]), "r"(a[3]), "r"(b[0]), "r"(b[1]));
}
__device__ __forceinline__ void ldm_x4(uint32_t& r0, uint32_t& r1,
                                       uint32_t& r2, uint32_t& r3,
                                       uint32_t addr) {
    asm volatile(
        "ldmatrix.sync.aligned.m8n8.x4.shared.b16 {%0,%1,%2,%3}, [%4];"
        : "=r"(r0), "=r"(r1), "=r"(r2), "=r"(r3) : "r"(addr));
}

// ===========================================================================
// Init: FIRE log tables
// ===========================================================================
__global__ void init_tables(const float* __restrict__ cp,
                            const float* __restrict__ lm) {
    const int i = blockIdx.x * blockDim.x + threadIdx.x;
    if (i >= TSEQ + UPAD) return;
    const float c = cp[0];
    const int   rel = i - UPAD;
    g_ut2[i] = logf(fabsf(c * (float)(rel < 0 ? 0 : rel)) + 1.0f);
    if (i < TSEQ) {
        const float thr = fabsf(lm[0] * 512.0f);
        g_invP[i] =
            1.0f / (logf(fabsf(c * fmaxf((float)i, thr)) + 1.0f) + 1e-6f);
    }
}

// ===========================================================================
// tf32 mma.sync GEMM, 4-stage cp.async pipeline (unchanged from R10 best).
// ===========================================================================
#define ABUF (128 * 20 * 4)
#define BBUF (16 * 136 * 4)
#define NSTG 4
#define GSMEM (NSTG * (ABUF + BBUF))

template <int MODE>
__global__ __launch_bounds__(256, 2) void mma_gemm(const float* __restrict__ A,
                                                   const float* __restrict__ Bm,
                                                   const float* __restrict__ bias,
                                                   float* __restrict__ out,
                                                   int K, int N) {
    extern __shared__ char sm[];
    const uint32_t sbase = smem_u32(sm);

    const int tid   = threadIdx.x;
    const int lane  = tid & 31;
    const int wid   = tid >> 5;
    const int warpM = wid & 3;
    const int warpN = wid >> 2;
    const int m0    = blockIdx.y * 128;
    const int n0    = blockIdx.x * 128;

    const int ar = tid >> 2;
    const int ak = (tid & 3) * 4;
    const float* Ag = A + (size_t)(m0 + ar) * K + ak;
    const int br = tid >> 4;
    const int bc = (tid & 15) * 4;
    const float* Bg = Bm + (size_t)br * N + n0 + bc;

    const uint32_t aOff0 = (uint32_t)(ar * 20 + ak) * 4;
    const uint32_t aOff1 = (uint32_t)((ar + 64) * 20 + ak) * 4;
    const uint32_t bOff0 = (uint32_t)(br * 136 + bc) * 4;
    const uint32_t bOff1 = (uint32_t)(br * 136 + bc + 64) * 4;

#define LOADTILE(st, kc)                                                      \
    do {                                                                      \
        const uint32_t as = sbase + (st) * ABUF;                              \
        const uint32_t bs = sbase + NSTG * ABUF + (st) * BBUF;                \
        CP_ASYNC16(as + aOff0, Ag + (kc) * 16);                               \
        CP_ASYNC16(as + aOff1, Ag + (size_t)64 * K + (kc) * 16);              \
        CP_ASYNC16(bs + bOff0, Bg + (size_t)(kc) * 16 * N);                   \
        CP_ASYNC16(bs + bOff1, Bg + (size_t)(kc) * 16 * N + 64);              \
        CP_COMMIT();                                                          \
    } while (0)

    float acc[2][8][4];
#pragma unroll
    for (int mf = 0; mf < 2; mf++)
#pragma unroll
        for (int nf = 0; nf < 8; nf++)
#pragma unroll
            for (int i = 0; i < 4; i++) acc[mf][nf][i] = 0.0f;

    const int r  = lane >> 2;
    const int cq = lane & 3;
    const int nk = K >> 4;

    LOADTILE(0, 0);
    LOADTILE(1, 1);
    LOADTILE(2, 2);

#pragma unroll 1
    for (int it = 0; it < nk; it++) {
        const int st  = it & (NSTG - 1);
        const int rem = nk - 1 - it;
        if (rem >= 2)      CP_WAIT(2);
        else if (rem == 1) CP_WAIT(1);
        else               CP_WAIT(0);
        __syncthreads();

        const float* Asf = (const float*)(sm + st * ABUF);
        const float* Bsf = (const float*)(sm + NSTG * ABUF + st * BBUF);

#pragma unroll
        for (int ks = 0; ks < 2; ks++) {
            const int kb = ks * 8;
            uint32_t af[2][4];
#pragma unroll
            for (int mf = 0; mf < 2; mf++) {
                const int mrow = warpM * 32 + mf * 16 + r;
                af[mf][0] = f2tf32(Asf[mrow * 20 + kb + cq]);
                af[mf][1] = f2tf32(Asf[(mrow + 8) * 20 + kb + cq]);
                af[mf][2] = f2tf32(Asf[mrow * 20 + kb + cq + 4]);
                af[mf][3] = f2tf32(Asf[(mrow + 8) * 20 + kb + cq + 4]);
            }
#pragma unroll
            for (int nf = 0; nf < 8; nf++) {
                const int ncol = warpN * 64 + nf * 8 + r;
                uint32_t bfr[2];
                bfr[0] = f2tf32(Bsf[(kb + cq) * 136 + ncol]);
                bfr[1] = f2tf32(Bsf[(kb + cq + 4) * 136 + ncol]);
                mma8(acc[0][nf], af[0], bfr);
                mma8(acc[1][nf], af[1], bfr);
            }
        }

        if (it + 3 < nk) LOADTILE((it + 3) & (NSTG - 1), it + 3);
    }
#undef LOADTILE

#pragma unroll
    for (int mf = 0; mf < 2; mf++) {
#pragma unroll
        for (int nf = 0; nf < 8; nf++) {
            const int n = n0 + warpN * 64 + nf * 8 + 2 * cq;
            const float bx = bias[n], by = bias[n + 1];
#pragma unroll
            for (int half = 0; half < 2; half++) {
                const int m = m0 + warpM * 32 + mf * 16 + r + half * 8;
                float2 v = make_float2(acc[mf][nf][half * 2] + bx,
                                       acc[mf][nf][half * 2 + 1] + by);
                if (MODE == 0) {
                    const int which = n >> 10;
                    const int hh    = (n & 1023) >> 6;
                    const int d     = n & 63;
                    const int bb    = m >> 11;
                    const int t     = m & 2047;
                    *(float2*)&g_qkv[which * (BSZ * NH * TSEQ * HD) +
                                     ((bb * NH + hh) * TSEQ + t) * HD + d] = v;
                } else {
                    *(float2*)&out[(size_t)m * N + n] = v;
                }
            }
        }
    }
}

// ===========================================================================
// FA2-style flash attention (R10 structure: Q in regs, no min-blocks bound),
// R12: 64-key tiles (half the rescale/sync overhead per key) + log2e folded
// into Q/bias so exp = bare ex2.approx.
// Dynamic smem (floats): Ks[2][64][68] @0, Vt[2][64][68] @8704, weights @17408.
// ===========================================================================
#define TSK    64
#define AT_VT  (2 * 64 * 68)
#define AT_W   (AT_VT + 2 * 64 * 68)
#define ASMEM  ((AT_W + 104) * 4)

__device__ __forceinline__ float fire_mlp(float nd, const float* sw1,
                                          const float* sb1, const float* sw2) {
    float acc = 0.0f;
#pragma unroll
    for (int w = 0; w < MLPW; w++)
        acc = fmaf(fmaxf(fmaf(nd, sw1[w], sb1[w]), 0.0f), sw2[w], acc);
    return acc;
}

__global__ __launch_bounds__(256) void attn_mma(
        const float* __restrict__ w1, const float* __restrict__ b1,
        const float* __restrict__ w2) {
    extern __shared__ float af_[];
    float* Ksm = af_;            // [buf][key 64][68]
    float* Vtm = af_ + AT_VT;    // [buf][d 64][68]  (cols = keys + 4 pad)
    float* sw1 = af_ + AT_W;
    float* sb1 = sw1 + MLPW;
    float* sw2 = sb1 + MLPW;
    float* sA  = sw2 + MLPW;     // [0]=alpha, [1]=lin

    const int tid  = threadIdx.x;
    const int lane = tid & 31;
    const int warp = tid >> 5;
    const int h    = blockIdx.y;
    const int b    = blockIdx.z;
    const int q0   = (gridDim.x - 1 - blockIdx.x) * 128;  // heavy blocks first
    const int tw   = q0 + warp * 16;
    const int r    = lane >> 2;
    const int cq   = lane & 3;
    const int t0   = tw + r;
    const int t1   = t0 + 8;

    if (tid < MLPW) {
        sw1[tid] = w1[tid];
        sb1[tid] = b1[tid];
        sw2[tid] = w2[tid * NH + h];
    }
    __syncthreads();
    if (tid == 0) {
        bool  lin = true;
        float a   = 0.0f;
#pragma unroll
        for (int w = 0; w < MLPW; w++) {
            lin = lin && (sb1[w] == 0.0f);
            a   = fmaf(fmaxf(sw1[w], 0.0f), sw2[w], a);
        }
        sA[0] = a;
        sA[1] = lin ? 1.0f : 0.0f;
    }

    const float invP0 = g_invP[t0];
    const float invP1 = g_invP[t1];

    const float* Qg = g_qkv + (size_t)(b * NH + h) * TSEQ * HD;
    const float* Kg = Qg + (size_t)BSZ * NH * TSEQ * HD;
    const float* Vg = Kg + (size_t)BSZ * NH * TSEQ * HD;

    // Q a-frags in regs, pre-scaled by log2e/sqrt(hd), tf32 rna
    const float qsc = 0.125f * LOG2E;
    uint32_t qa[8][4];
#pragma unroll
    for (int kf = 0; kf < 8; kf++) {
        qa[kf][0] = f2tf32(Qg[(size_t)t0 * HD + kf * 8 + cq] * qsc);
        qa[kf][1] = f2tf32(Qg[(size_t)t1 * HD + kf * 8 + cq] * qsc);
        qa[kf][2] = f2tf32(Qg[(size_t)t0 * HD + kf * 8 + cq + 4] * qsc);
        qa[kf][3] = f2tf32(Qg[(size_t)t1 * HD + kf * 8 + cq + 4] * qsc);
    }

    float o[8][4];
#pragma unroll
    for (int nd = 0; nd < 8; nd++)
#pragma unroll
        for (int i = 0; i < 4; i++) o[nd][i] = 0.0f;
    float m0 = -1e30f, m1 = -1e30f, l0 = 0.0f, l1 = 0.0f;

    // Staging: thread owns key rows krow and krow+32, d-phase kc
    const int krow = tid >> 3;   // 0..31
    const int kc   = tid & 7;
    float4 ka0, ka1, kb0, kb1;
    float  va[8], vbr[8];

#define KV_LDG(s0)                                                            \
    do {                                                                      \
        const float4* kpA = (const float4*)&Kg[(size_t)((s0) + krow) * HD];   \
        const float4* kpB = kpA + 32 * (HD / 4);                              \
        ka0 = kpA[kc]; ka1 = kpA[kc + 8];                                     \
        kb0 = kpB[kc]; kb1 = kpB[kc + 8];                                     \
        _Pragma("unroll")                                                     \
        for (int i = 0; i < 8; i++) {                                         \
            va[i]  = Vg[(size_t)((s0) + krow) * HD + kc + 8 * i];             \
            vbr[i] = Vg[(size_t)((s0) + krow + 32) * HD + kc + 8 * i];        \
        }                                                                     \
    } while (0)

#define KV_STS(buf)                                                           \
    do {                                                                      \
        float* kdst = Ksm + (buf) * (64 * 68);                                \
        float* vdst = Vtm + (buf) * (64 * 68);                                \
        *(float4*)&kdst[krow * 68 + kc * 4] =                                 \
            make_float4(rnaf(ka0.x), rnaf(ka0.y), rnaf(ka0.z), rnaf(ka0.w));  \
        *(float4*)&kdst[krow * 68 + kc * 4 + 32] =                            \
            make_float4(rnaf(ka1.x), rnaf(ka1.y), rnaf(ka1.z), rnaf(ka1.w));  \
        *(float4*)&kdst[(krow + 32) * 68 + kc * 4] =                          \
            make_float4(rnaf(kb0.x), rnaf(kb0.y), rnaf(kb0.z), rnaf(kb0.w));  \
        *(float4*)&kdst[(krow + 32) * 68 + kc * 4 + 32] =                     \
            make_float4(rnaf(kb1.x), rnaf(kb1.y), rnaf(kb1.z), rnaf(kb1.w));  \
        _Pragma("unroll")                                                     \
        for (int i = 0; i < 8; i++) {                                         \
            vdst[(kc + 8 * i) * 68 + krow]      = rnaf(va[i]);                \
            vdst[(kc + 8 * i) * 68 + krow + 32] = rnaf(vbr[i]);               \
        }                                                                     \
    } while (0)

    KV_LDG(0);
    KV_STS(0);
    __syncthreads();

    const float alpha = sA[0];
    const int   lin   = (sA[1] != 0.0f);
    const float ai0   = alpha * invP0 * LOG2E;
    const float ai1   = alpha * invP1 * LOG2E;
    const float* ut   = g_ut2 + UPAD;

    const int nt = (q0 + 128) >> 6;   // 64-key tiles
#pragma unroll 1
    for (int it = 0; it < nt; it++) {
        const int  buf = it & 1;
        const int  s0  = it * TSK;
        const bool nxt = (it + 1) < nt;

        if (nxt) KV_LDG(s0 + TSK);

        if (s0 <= tw + 15) {
            const bool     msk = (s0 + TSK - 1) > tw;
            const uint32_t kb  = smem_u32(Ksm + buf * (64 * 68));
            const uint32_t vb  = smem_u32(Vtm + buf * (64 * 68));

            // ---- QK^T: 8 nf x 4 kfp ----
            float s[8][4];
#pragma unroll
            for (int nf = 0; nf < 8; nf++)
                s[nf][0] = s[nf][1] = s[nf][2] = s[nf][3] = 0.0f;
#pragma unroll
            for (int kfp = 0; kfp < 4; kfp++) {
#pragma unroll
                for (int nf = 0; nf < 8; nf++) {
                    uint32_t bb[4];
                    const uint32_t addr = kb +
                        4u * ((uint32_t)(8 * nf + (lane & 7)) * 68u +
                              16u * kfp + 4u * (lane >> 3));
                    ldm_x4(bb[0], bb[1], bb[2], bb[3], addr);
                    mma8(s[nf], qa[2 * kfp], bb);
                    mma8(s[nf], qa[2 * kfp + 1], bb + 2);
                }
            }

            // ---- bias (log2 units) + mask + tile max ----
            float mt0 = -1e30f, mt1 = -1e30f;
#pragma unroll
            for (int nf = 0; nf < 8; nf++) {
                const int k0    = s0 + nf * 8 + 2 * cq;
                const int rel00 = t0 - k0;
                const float u00 = __ldg(&ut[rel00]);
                const float u01 = __ldg(&ut[rel00 - 1]);
                const float u10 = __ldg(&ut[rel00 + 8]);
                const float u11 = __ldg(&ut[rel00 + 7]);
                if (lin) {
                    s[nf][0] = fmaf(ai0, u00, s[nf][0]);
                    s[nf][1] = fmaf(ai0, u01, s[nf][1]);
                    s[nf][2] = fmaf(ai1, u10, s[nf][2]);
                    s[nf][3] = fmaf(ai1, u11, s[nf][3]);
                } else {
                    s[nf][0] = fmaf(fire_mlp(u00 * invP0, sw1, sb1, sw2), LOG2E, s[nf][0]);
                    s[nf][1] = fmaf(fire_mlp(u01 * invP0, sw1, sb1, sw2), LOG2E, s[nf][1]);
                    s[nf][2] = fmaf(fire_mlp(u10 * invP1, sw1, sb1, sw2), LOG2E, s[nf][2]);
                    s[nf][3] = fmaf(fire_mlp(u11 * invP1, sw1, sb1, sw2), LOG2E, s[nf][3]);
                }
                if (msk) {
                    if (rel00 < 0)     s[nf][0] = -1e30f;
                    if (rel00 - 1 < 0) s[nf][1] = -1e30f;
                    if (rel00 + 8 < 0) s[nf][2] = -1e30f;
                    if (rel00 + 7 < 0) s[nf][3] = -1e30f;
                }
                mt0 = fmaxf(mt0, fmaxf(s[nf][0], s[nf][1]));
                mt1 = fmaxf(mt1, fmaxf(s[nf][2], s[nf][3]));
            }
            mt0 = fmaxf(mt0, __shfl_xor_sync(0xffffffffu, mt0, 1));
            mt0 = fmaxf(mt0, __shfl_xor_sync(0xffffffffu, mt0, 2));
            mt1 = fmaxf(mt1, __shfl_xor_sync(0xffffffffu, mt1, 1));
            mt1 = fmaxf(mt1, __shfl_xor_sync(0xffffffffu, mt1, 2));

            const float mn0 = fmaxf(m0, mt0);
            const float mn1 = fmaxf(m1, mt1);
            const float f0  = ex2(m0 - mn0);
            const float f1  = ex2(m1 - mn1);
            m0 = mn0; m1 = mn1;
            l0 *= f0;  l1 *= f1;
#pragma unroll
            for (int nd = 0; nd < 8; nd++) {
                o[nd][0] *= f0; o[nd][1] *= f0;
                o[nd][2] *= f1; o[nd][3] *= f1;
            }
#pragma unroll
            for (int nf = 0; nf < 8; nf++) {
                s[nf][0] = ex2(s[nf][0] - m0);
                s[nf][1] = ex2(s[nf][1] - m0);
                s[nf][2] = ex2(s[nf][2] - m1);
                s[nf][3] = ex2(s[nf][3] - m1);
                l0 += s[nf][0] + s[nf][1];
                l1 += s[nf][2] + s[nf][3];
            }

            // ---- PV: 8 kf2 x 4 g ----
            const int src1 = (lane & 28) | (cq >> 1);
            const int src2 = src1 + 2;
#pragma unroll
            for (int kf2 = 0; kf2 < 8; kf2++) {
                const float x0 = __shfl_sync(0xffffffffu, s[kf2][0], src1);
                const float x1 = __shfl_sync(0xffffffffu, s[kf2][1], src1);
                const float y0 = __shfl_sync(0xffffffffu, s[kf2][0], src2);
                const float y1 = __shfl_sync(0xffffffffu, s[kf2][1], src2);
                const float x2 = __shfl_sync(0xffffffffu, s[kf2][2], src1);
                const float x3 = __shfl_sync(0xffffffffu, s[kf2][3], src1);
                const float y2 = __shfl_sync(0xffffffffu, s[kf2][2], src2);
                const float y3 = __shfl_sync(0xffffffffu, s[kf2][3], src2);
                uint32_t pa[4];
                pa[0] = f2tf32((cq & 1) ? x1 : x0);
                pa[1] = f2tf32((cq & 1) ? x3 : x2);
                pa[2] = f2tf32((cq & 1) ? y1 : y0);
                pa[3] = f2tf32((cq & 1) ? y3 : y2);
#pragma unroll
                for (int g = 0; g < 4; g++) {
                    uint32_t bv[4];
                    const uint32_t addr = vb +
                        4u * ((uint32_t)(8 * (2 * g + (lane >> 4)) + (lane & 7)) * 68u +
                              8u * kf2 + 4u * ((lane >> 3) & 1));
                    ldm_x4(bv[0], bv[1], bv[2], bv[3], addr);
                    mma8(o[2 * g], pa, bv);
                    mma8(o[2 * g + 1], pa, bv + 2);
                }
            }
        }

        if (nxt) KV_STS(buf ^ 1);
        __syncthreads();
    }
#undef KV_LDG
#undef KV_STS

    l0 += __shfl_xor_sync(0xffffffffu, l0, 1);
    l0 += __shfl_xor_sync(0xffffffffu, l0, 2);
    l1 += __shfl_xor_sync(0xffffffffu, l1, 1);
    l1 += __shfl_xor_sync(0xffffffffu, l1, 2);
    const float inv0 = 1.0f / l0;
    const float inv1 = 1.0f / l1;
    float* y0p = &g_y[((size_t)(b * TSEQ) + t0) * CDIM + h * HD];
    float* y1p = &g_y[((size_t)(b * TSEQ) + t1) * CDIM + h * HD];
#pragma unroll
    for (int nd = 0; nd < 8; nd++) {
        const int d = nd * 8 + 2 * cq;
        *(float2*)&y0p[d] = make_float2(o[nd][0] * inv0, o[nd][1] * inv0);
        *(float2*)&y1p[d] = make_float2(o[nd][2] * inv1, o[nd][3] * inv1);
    }
}

// ===========================================================================
// Launch
// ===========================================================================
extern "C" void kernel_launch(void* const* d_in, const int* in_sizes, int n_in,
                              void* d_out, int out_size) {
    const float* x     = (const float*)d_in[0];
    const float* Wqkv  = (const float*)d_in[1];
    const float* bqkv  = (const float*)d_in[2];
    const float* Wproj = (const float*)d_in[3];
    const float* bproj = (const float*)d_in[4];
    const float* w1    = (const float*)d_in[5];
    const float* b1    = (const float*)d_in[6];
    const float* w2    = (const float*)d_in[7];
    const float* cpar  = (const float*)d_in[9];
    const float* lmul  = (const float*)d_in[10];
    float* out = (float*)d_out;

    cudaFuncSetAttribute(mma_gemm<0>,
                         cudaFuncAttributeMaxDynamicSharedMemorySize, GSMEM);
    cudaFuncSetAttribute(mma_gemm<1>,
                         cudaFuncAttributeMaxDynamicSharedMemorySize, GSMEM);
    cudaFuncSetAttribute(attn_mma,
                         cudaFuncAttributeMaxDynamicSharedMemorySize, ASMEM);

    init_tables<<<(TSEQ + UPAD + 255) / 256, 256>>>(cpar, lmul);

    mma_gemm<0><<<dim3(3 * CDIM / 128, BSZ * TSEQ / 128), 256, GSMEM>>>(
        x, Wqkv, bqkv, nullptr, CDIM, 3 * CDIM);

    attn_mma<<<dim3(TSEQ / 128, NH, BSZ), 256, ASMEM>>>(w1, b1, w2);

    float* gy_ptr = nullptr;
    cudaGetSymbolAddress((void**)&gy_ptr, g_y);
    mma_gemm<1><<<dim3(CDIM / 128, BSZ * TSEQ / 128), 256, GSMEM>>>(
        gy_ptr, Wproj, bproj, out, CDIM, CDIM);
}

// round 13
// speedup vs baseline: 1.2838x; 1.0424x over previous
#include <cuda_runtime.h>
#include <cstdint>

// Problem constants (B=2, T=2048, C=1024, H=16, hd=64, MLP width 32)
#define BSZ   2
#define TSEQ  2048
#define CDIM  1024
#define NH    16
#define HD    64
#define MLPW  32
#define UPAD  64
#define LOG2E 1.4426950408889634f

__device__ float g_qkv[3 * BSZ * NH * TSEQ * HD];   // tf32-rounded QKV
__device__ float g_y[BSZ * TSEQ * CDIM];            // tf32-rounded attn out
__device__ float g_ut2[TSEQ + UPAD];
__device__ float g_invP[TSEQ];
// tf32-pre-rounded GEMM inputs
__device__ float g_xr[BSZ * TSEQ * CDIM];           // 4M
__device__ float g_wqkvr[CDIM * 3 * CDIM];          // 3M
__device__ float g_wprojr[CDIM * CDIM];             // 1M

// ===========================================================================
// Helpers
// ===========================================================================
__device__ __forceinline__ uint32_t smem_u32(const void* p) {
    uint32_t a;
    asm("{ .reg .u64 t; cvta.to.shared.u64 t, %1; cvt.u32.u64 %0, t; }"
        : "=r"(a) : "l"(p));
    return a;
}
#define CP_ASYNC16(dst, src) \
    asm volatile("cp.async.cg.shared.global [%0], [%1], 16;" \
                 :: "r"(dst), "l"(src) : "memory")
#define CP_COMMIT() asm volatile("cp.async.commit_group;" ::: "memory")
#define CP_WAIT(n)  asm volatile("cp.async.wait_group %0;" :: "n"(n) : "memory")

__device__ __forceinline__ uint32_t f2tf32(float f) {
    uint32_t r;
    asm("cvt.rna.tf32.f32 %0, %1;" : "=r"(r) : "f"(f));
    return r;
}
__device__ __forceinline__ float rnaf(float f) {
    return __uint_as_float(f2tf32(f));
}
__device__ __forceinline__ float ex2(float x) {
    float y;
    asm("ex2.approx.f32 %0, %1;" : "=f"(y) : "f"(x));
    return y;
}
__device__ __forceinline__ void mma8(float* c, const uint32_t* a,
                                     const uint32_t* b) {
    asm volatile(
        "mma.sync.aligned.m16n8k8.row.col.f32.tf32.tf32.f32 "
        "{%0,%1,%2,%3}, {%4,%5,%6,%7}, {%8,%9}, {%0,%1,%2,%3};"
        : "+f"(c[0]), "+f"(c[1]), "+f"(c[2]), "+f"(c[3])
        : "r"(a[0]), "r"(a[1]), "r"(a[2]), "r"(a[3]), "r"(b[0]), "r"(b[1]));
}
__device__ __forceinline__ void ldm_x4(uint32_t& r0, uint32_t& r1,
                                       uint32_t& r2, uint32_t& r3,
                                       uint32_t addr) {
    asm volatile(
        "ldmatrix.sync.aligned.m8n8.x4.shared.b16 {%0,%1,%2,%3}, [%4];"
        : "=r"(r0), "=r"(r1), "=r"(r2), "=r"(r3) : "r"(addr));
}

// ===========================================================================
// Init kernels
// ===========================================================================
__global__ void init_tables(const float* __restrict__ cp,
                            const float* __restrict__ lm) {
    const int i = blockIdx.x * blockDim.x + threadIdx.x;
    if (i >= TSEQ + UPAD) return;
    const float c = cp[0];
    const int   rel = i - UPAD;
    g_ut2[i] = logf(fabsf(c * (float)(rel < 0 ? 0 : rel)) + 1.0f);
    if (i < TSEQ) {
        const float thr = fabsf(lm[0] * 512.0f);
        g_invP[i] =
            1.0f / (logf(fabsf(c * fmaxf((float)i, thr)) + 1.0f) + 1e-6f);
    }
}

// Pre-round a float buffer to tf32 bits (rna). n4 = element count / 4.
__global__ void cvt_tf32(const float4* __restrict__ src,
                         float4* __restrict__ dst, int n4) {
    const int i = blockIdx.x * blockDim.x + threadIdx.x;
    if (i >= n4) return;
    float4 v = src[i];
    dst[i] = make_float4(rnaf(v.x), rnaf(v.y), rnaf(v.z), rnaf(v.w));
}

// ===========================================================================
// tf32 mma.sync GEMM, 4-stage cp.async pipeline. Inputs are PRE-ROUNDED to
// tf32 in gmem, so the mainloop has ZERO cvt — LDS bits feed HMMA directly.
// MODE 0 epilogue rounds its output (consumed as tf32 by attention).
// ===========================================================================
#define ABUF (128 * 20 * 4)
#define BBUF (16 * 136 * 4)
#define NSTG 4
#define GSMEM (NSTG * (ABUF + BBUF))

template <int MODE>
__global__ __launch_bounds__(256, 2) void mma_gemm(const float* __restrict__ A,
                                                   const float* __restrict__ Bm,
                                                   const float* __restrict__ bias,
                                                   float* __restrict__ out,
                                                   int K, int N) {
    extern __shared__ char sm[];
    const uint32_t sbase = smem_u32(sm);

    const int tid   = threadIdx.x;
    const int lane  = tid & 31;
    const int wid   = tid >> 5;
    const int warpM = wid & 3;
    const int warpN = wid >> 2;
    const int m0    = blockIdx.y * 128;
    const int n0    = blockIdx.x * 128;

    const int ar = tid >> 2;
    const int ak = (tid & 3) * 4;
    const float* Ag = A + (size_t)(m0 + ar) * K + ak;
    const int br = tid >> 4;
    const int bc = (tid & 15) * 4;
    const float* Bg = Bm + (size_t)br * N + n0 + bc;

    const uint32_t aOff0 = (uint32_t)(ar * 20 + ak) * 4;
    const uint32_t aOff1 = (uint32_t)((ar + 64) * 20 + ak) * 4;
    const uint32_t bOff0 = (uint32_t)(br * 136 + bc) * 4;
    const uint32_t bOff1 = (uint32_t)(br * 136 + bc + 64) * 4;

#define LOADTILE(st, kc)                                                      \
    do {                                                                      \
        const uint32_t as = sbase + (st) * ABUF;                              \
        const uint32_t bs = sbase + NSTG * ABUF + (st) * BBUF;                \
        CP_ASYNC16(as + aOff0, Ag + (kc) * 16);                               \
        CP_ASYNC16(as + aOff1, Ag + (size_t)64 * K + (kc) * 16);              \
        CP_ASYNC16(bs + bOff0, Bg + (size_t)(kc) * 16 * N);                   \
        CP_ASYNC16(bs + bOff1, Bg + (size_t)(kc) * 16 * N + 64);              \
        CP_COMMIT();                                                          \
    } while (0)

    float acc[2][8][4];
#pragma unroll
    for (int mf = 0; mf < 2; mf++)
#pragma unroll
        for (int nf = 0; nf < 8; nf++)
#pragma unroll
            for (int i = 0; i < 4; i++) acc[mf][nf][i] = 0.0f;

    const int r  = lane >> 2;
    const int cq = lane & 3;
    const int nk = K >> 4;

    LOADTILE(0, 0);
    LOADTILE(1, 1);
    LOADTILE(2, 2);

#pragma unroll 1
    for (int it = 0; it < nk; it++) {
        const int st  = it & (NSTG - 1);
        const int rem = nk - 1 - it;
        if (rem >= 2)      CP_WAIT(2);
        else if (rem == 1) CP_WAIT(1);
        else               CP_WAIT(0);
        __syncthreads();

        const uint32_t* Asf = (const uint32_t*)(sm + st * ABUF);
        const uint32_t* Bsf = (const uint32_t*)(sm + NSTG * ABUF + st * BBUF);

#pragma unroll
        for (int ks = 0; ks < 2; ks++) {
            const int kb = ks * 8;
            uint32_t af[2][4];
#pragma unroll
            for (int mf = 0; mf < 2; mf++) {
                const int mrow = warpM * 32 + mf * 16 + r;
                af[mf][0] = Asf[mrow * 20 + kb + cq];
                af[mf][1] = Asf[(mrow + 8) * 20 + kb + cq];
                af[mf][2] = Asf[mrow * 20 + kb + cq + 4];
                af[mf][3] = Asf[(mrow + 8) * 20 + kb + cq + 4];
            }
#pragma unroll
            for (int nf = 0; nf < 8; nf++) {
                const int ncol = warpN * 64 + nf * 8 + r;
                uint32_t bfr[2];
                bfr[0] = Bsf[(kb + cq) * 136 + ncol];
                bfr[1] = Bsf[(kb + cq + 4) * 136 + ncol];
                mma8(acc[0][nf], af[0], bfr);
                mma8(acc[1][nf], af[1], bfr);
            }
        }

        if (it + 3 < nk) LOADTILE((it + 3) & (NSTG - 1), it + 3);
    }
#undef LOADTILE

#pragma unroll
    for (int mf = 0; mf < 2; mf++) {
#pragma unroll
        for (int nf = 0; nf < 8; nf++) {
            const int n = n0 + warpN * 64 + nf * 8 + 2 * cq;
            const float bx = bias[n], by = bias[n + 1];
#pragma unroll
            for (int half = 0; half < 2; half++) {
                const int m = m0 + warpM * 32 + mf * 16 + r + half * 8;
                float2 v = make_float2(acc[mf][nf][half * 2] + bx,
                                       acc[mf][nf][half * 2 + 1] + by);
                if (MODE == 0) {
                    // round here once; attention consumes tf32 bits directly
                    v.x = rnaf(v.x);
                    v.y = rnaf(v.y);
                    const int which = n >> 10;
                    const int hh    = (n & 1023) >> 6;
                    const int d     = n & 63;
                    const int bb    = m >> 11;
                    const int t     = m & 2047;
                    *(float2*)&g_qkv[which * (BSZ * NH * TSEQ * HD) +
                                     ((bb * NH + hh) * TSEQ + t) * HD + d] = v;
                } else {
                    *(float2*)&out[(size_t)m * N + n] = v;
                }
            }
        }
    }
}

// ===========================================================================
// FA2-style flash attention (R12 structure: 64-key tiles, Q in regs, ex2).
// K/V arrive pre-rounded from the QKV epilogue -> staging is a raw copy.
// Output store rounds to tf32 for the proj GEMM.
// ===========================================================================
#define TSK    64
#define AT_VT  (2 * 64 * 68)
#define AT_W   (AT_VT + 2 * 64 * 68)
#define ASMEM  ((AT_W + 104) * 4)

__device__ __forceinline__ float fire_mlp(float nd, const float* sw1,
                                          const float* sb1, const float* sw2) {
    float acc = 0.0f;
#pragma unroll
    for (int w = 0; w < MLPW; w++)
        acc = fmaf(fmaxf(fmaf(nd, sw1[w], sb1[w]), 0.0f), sw2[w], acc);
    return acc;
}

__global__ __launch_bounds__(256) void attn_mma(
        const float* __restrict__ w1, const float* __restrict__ b1,
        const float* __restrict__ w2) {
    extern __shared__ float af_[];
    float* Ksm = af_;
    float* Vtm = af_ + AT_VT;
    float* sw1 = af_ + AT_W;
    float* sb1 = sw1 + MLPW;
    float* sw2 = sb1 + MLPW;
    float* sA  = sw2 + MLPW;

    const int tid  = threadIdx.x;
    const int lane = tid & 31;
    const int warp = tid >> 5;
    const int h    = blockIdx.y;
    const int b    = blockIdx.z;
    const int q0   = (gridDim.x - 1 - blockIdx.x) * 128;
    const int tw   = q0 + warp * 16;
    const int r    = lane >> 2;
    const int cq   = lane & 3;
    const int t0   = tw + r;
    const int t1   = t0 + 8;

    if (tid < MLPW) {
        sw1[tid] = w1[tid];
        sb1[tid] = b1[tid];
        sw2[tid] = w2[tid * NH + h];
    }
    __syncthreads();
    if (tid == 0) {
        bool  lin = true;
        float a   = 0.0f;
#pragma unroll
        for (int w = 0; w < MLPW; w++) {
            lin = lin && (sb1[w] == 0.0f);
            a   = fmaf(fmaxf(sw1[w], 0.0f), sw2[w], a);
        }
        sA[0] = a;
        sA[1] = lin ? 1.0f : 0.0f;
    }

    const float invP0 = g_invP[t0];
    const float invP1 = g_invP[t1];

    const float* Qg = g_qkv + (size_t)(b * NH + h) * TSEQ * HD;
    const float* Kg = Qg + (size_t)BSZ * NH * TSEQ * HD;
    const float* Vg = Kg + (size_t)BSZ * NH * TSEQ * HD;

    // Q a-frags, scaled by log2e/sqrt(hd) then re-rounded (scale reintroduces
    // low bits; keep the rna here)
    const float qsc = 0.125f * LOG2E;
    uint32_t qa[8][4];
#pragma unroll
    for (int kf = 0; kf < 8; kf++) {
        qa[kf][0] = f2tf32(Qg[(size_t)t0 * HD + kf * 8 + cq] * qsc);
        qa[kf][1] = f2tf32(Qg[(size_t)t1 * HD + kf * 8 + cq] * qsc);
        qa[kf][2] = f2tf32(Qg[(size_t)t0 * HD + kf * 8 + cq + 4] * qsc);
        qa[kf][3] = f2tf32(Qg[(size_t)t1 * HD + kf * 8 + cq + 4] * qsc);
    }

    float o[8][4];
#pragma unroll
    for (int nd = 0; nd < 8; nd++)
#pragma unroll
        for (int i = 0; i < 4; i++) o[nd][i] = 0.0f;
    float m0 = -1e30f, m1 = -1e30f, l0 = 0.0f, l1 = 0.0f;

    const int krow = tid >> 3;
    const int kc   = tid & 7;
    float4 ka0, ka1, kb0, kb1;
    float  va[8], vbr[8];

#define KV_LDG(s0)                                                            \
    do {                                                                      \
        const float4* kpA = (const float4*)&Kg[(size_t)((s0) + krow) * HD];   \
        const float4* kpB = kpA + 32 * (HD / 4);                              \
        ka0 = kpA[kc]; ka1 = kpA[kc + 8];                                     \
        kb0 = kpB[kc]; kb1 = kpB[kc + 8];                                     \
        _Pragma("unroll")                                                     \
        for (int i = 0; i < 8; i++) {                                         \
            va[i]  = Vg[(size_t)((s0) + krow) * HD + kc + 8 * i];             \
            vbr[i] = Vg[(size_t)((s0) + krow + 32) * HD + kc + 8 * i];        \
        }                                                                     \
    } while (0)

#define KV_STS(buf)                                                           \
    do {                                                                      \
        float* kdst = Ksm + (buf) * (64 * 68);                                \
        float* vdst = Vtm + (buf) * (64 * 68);                                \
        *(float4*)&kdst[krow * 68 + kc * 4]             = ka0;                \
        *(float4*)&kdst[krow * 68 + kc * 4 + 32]        = ka1;                \
        *(float4*)&kdst[(krow + 32) * 68 + kc * 4]      = kb0;                \
        *(float4*)&kdst[(krow + 32) * 68 + kc * 4 + 32] = kb1;                \
        _Pragma("unroll")                                                     \
        for (int i = 0; i < 8; i++) {                                         \
            vdst[(kc + 8 * i) * 68 + krow]      = va[i];                      \
            vdst[(kc + 8 * i) * 68 + krow + 32] = vbr[i];                     \
        }                                                                     \
    } while (0)

    KV_LDG(0);
    KV_STS(0);
    __syncthreads();

    const float alpha = sA[0];
    const int   lin   = (sA[1] != 0.0f);
    const float ai0   = alpha * invP0 * LOG2E;
    const float ai1   = alpha * invP1 * LOG2E;
    const float* ut   = g_ut2 + UPAD;

    const int nt = (q0 + 128) >> 6;
#pragma unroll 1
    for (int it = 0; it < nt; it++) {
        const int  buf = it & 1;
        const int  s0  = it * TSK;
        const bool nxt = (it + 1) < nt;

        if (nxt) KV_LDG(s0 + TSK);

        if (s0 <= tw + 15) {
            const bool     msk = (s0 + TSK - 1) > tw;
            const uint32_t kb  = smem_u32(Ksm + buf * (64 * 68));
            const uint32_t vb  = smem_u32(Vtm + buf * (64 * 68));

            float s[8][4];
#pragma unroll
            for (int nf = 0; nf < 8; nf++)
                s[nf][0] = s[nf][1] = s[nf][2] = s[nf][3] = 0.0f;
#pragma unroll
            for (int kfp = 0; kfp < 4; kfp++) {
#pragma unroll
                for (int nf = 0; nf < 8; nf++) {
                    uint32_t bb[4];
                    const uint32_t addr = kb +
                        4u * ((uint32_t)(8 * nf + (lane & 7)) * 68u +
                              16u * kfp + 4u * (lane >> 3));
                    ldm_x4(bb[0], bb[1], bb[2], bb[3], addr);
                    mma8(s[nf], qa[2 * kfp], bb);
                    mma8(s[nf], qa[2 * kfp + 1], bb + 2);
                }
            }

            float mt0 = -1e30f, mt1 = -1e30f;
#pragma unroll
            for (int nf = 0; nf < 8; nf++) {
                const int k0    = s0 + nf * 8 + 2 * cq;
                const int rel00 = t0 - k0;
                const float u00 = __ldg(&ut[rel00]);
                const float u01 = __ldg(&ut[rel00 - 1]);
                const float u10 = __ldg(&ut[rel00 + 8]);
                const float u11 = __ldg(&ut[rel00 + 7]);
                if (lin) {
                    s[nf][0] = fmaf(ai0, u00, s[nf][0]);
                    s[nf][1] = fmaf(ai0, u01, s[nf][1]);
                    s[nf][2] = fmaf(ai1, u10, s[nf][2]);
                    s[nf][3] = fmaf(ai1, u11, s[nf][3]);
                } else {
                    s[nf][0] = fmaf(fire_mlp(u00 * invP0, sw1, sb1, sw2), LOG2E, s[nf][0]);
                    s[nf][1] = fmaf(fire_mlp(u01 * invP0, sw1, sb1, sw2), LOG2E, s[nf][1]);
                    s[nf][2] = fmaf(fire_mlp(u10 * invP1, sw1, sb1, sw2), LOG2E, s[nf][2]);
                    s[nf][3] = fmaf(fire_mlp(u11 * invP1, sw1, sb1, sw2), LOG2E, s[nf][3]);
                }
                if (msk) {
                    if (rel00 < 0)     s[nf][0] = -1e30f;
                    if (rel00 - 1 < 0) s[nf][1] = -1e30f;
                    if (rel00 + 8 < 0) s[nf][2] = -1e30f;
                    if (rel00 + 7 < 0) s[nf][3] = -1e30f;
                }
                mt0 = fmaxf(mt0, fmaxf(s[nf][0], s[nf][1]));
                mt1 = fmaxf(mt1, fmaxf(s[nf][2], s[nf][3]));
            }
            mt0 = fmaxf(mt0, __shfl_xor_sync(0xffffffffu, mt0, 1));
            mt0 = fmaxf(mt0, __shfl_xor_sync(0xffffffffu, mt0, 2));
            mt1 = fmaxf(mt1, __shfl_xor_sync(0xffffffffu, mt1, 1));
            mt1 = fmaxf(mt1, __shfl_xor_sync(0xffffffffu, mt1, 2));

            const float mn0 = fmaxf(m0, mt0);
            const float mn1 = fmaxf(m1, mt1);
            const float f0  = ex2(m0 - mn0);
            const float f1  = ex2(m1 - mn1);
            m0 = mn0; m1 = mn1;
            l0 *= f0;  l1 *= f1;
#pragma unroll
            for (int nd = 0; nd < 8; nd++) {
                o[nd][0] *= f0; o[nd][1] *= f0;
                o[nd][2] *= f1; o[nd][3] *= f1;
            }
#pragma unroll
            for (int nf = 0; nf < 8; nf++) {
                s[nf][0] = ex2(s[nf][0] - m0);
                s[nf][1] = ex2(s[nf][1] - m0);
                s[nf][2] = ex2(s[nf][2] - m1);
                s[nf][3] = ex2(s[nf][3] - m1);
                l0 += s[nf][0] + s[nf][1];
                l1 += s[nf][2] + s[nf][3];
            }

            const int src1 = (lane & 28) | (cq >> 1);
            const int src2 = src1 + 2;
#pragma unroll
            for (int kf2 = 0; kf2 < 8; kf2++) {
                const float x0 = __shfl_sync(0xffffffffu, s[kf2][0], src1);
                const float x1 = __shfl_sync(0xffffffffu, s[kf2][1], src1);
                const float y0 = __shfl_sync(0xffffffffu, s[kf2][0], src2);
                const float y1 = __shfl_sync(0xffffffffu, s[kf2][1], src2);
                const float x2 = __shfl_sync(0xffffffffu, s[kf2][2], src1);
                const float x3 = __shfl_sync(0xffffffffu, s[kf2][3], src1);
                const float y2 = __shfl_sync(0xffffffffu, s[kf2][2], src2);
                const float y3 = __shfl_sync(0xffffffffu, s[kf2][3], src2);
                uint32_t pa[4];
                pa[0] = f2tf32((cq & 1) ? x1 : x0);
                pa[1] = f2tf32((cq & 1) ? x3 : x2);
                pa[2] = f2tf32((cq & 1) ? y1 : y0);
                pa[3] = f2tf32((cq & 1) ? y3 : y2);
#pragma unroll
                for (int g = 0; g < 4; g++) {
                    uint32_t bv[4];
                    const uint32_t addr = vb +
                        4u * ((uint32_t)(8 * (2 * g + (lane >> 4)) + (lane & 7)) * 68u +
                              8u * kf2 + 4u * ((lane >> 3) & 1));
                    ldm_x4(bv[0], bv[1], bv[2], bv[3], addr);
                    mma8(o[2 * g], pa, bv);
                    mma8(o[2 * g + 1], pa, bv + 2);
                }
            }
        }

        if (nxt) KV_STS(buf ^ 1);
        __syncthreads();
    }
#undef KV_LDG
#undef KV_STS

    l0 += __shfl_xor_sync(0xffffffffu, l0, 1);
    l0 += __shfl_xor_sync(0xffffffffu, l0, 2);
    l1 += __shfl_xor_sync(0xffffffffu, l1, 1);
    l1 += __shfl_xor_sync(0xffffffffu, l1, 2);
    const float inv0 = 1.0f / l0;
    const float inv1 = 1.0f / l1;
    float* y0p = &g_y[((size_t)(b * TSEQ) + t0) * CDIM + h * HD];
    float* y1p = &g_y[((size_t)(b * TSEQ) + t1) * CDIM + h * HD];
#pragma unroll
    for (int nd = 0; nd < 8; nd++) {
        const int d = nd * 8 + 2 * cq;
        // pre-round for the proj GEMM (same rounding it would apply)
        *(float2*)&y0p[d] = make_float2(rnaf(o[nd][0] * inv0), rnaf(o[nd][1] * inv0));
        *(float2*)&y1p[d] = make_float2(rnaf(o[nd][2] * inv1), rnaf(o[nd][3] * inv1));
    }
}

// ===========================================================================
// Launch
// ===========================================================================
extern "C" void kernel_launch(void* const* d_in, const int* in_sizes, int n_in,
                              void* d_out, int out_size) {
    const float* x     = (const float*)d_in[0];
    const float* Wqkv  = (const float*)d_in[1];
    const float* bqkv  = (const float*)d_in[2];
    const float* Wproj = (const float*)d_in[3];
    const float* bproj = (const float*)d_in[4];
    const float* w1    = (const float*)d_in[5];
    const float* b1    = (const float*)d_in[6];
    const float* w2    = (const float*)d_in[7];
    const float* cpar  = (const float*)d_in[9];
    const float* lmul  = (const float*)d_in[10];
    float* out = (float*)d_out;

    cudaFuncSetAttribute(mma_gemm<0>,
                         cudaFuncAttributeMaxDynamicSharedMemorySize, GSMEM);
    cudaFuncSetAttribute(mma_gemm<1>,
                         cudaFuncAttributeMaxDynamicSharedMemorySize, GSMEM);
    cudaFuncSetAttribute(attn_mma,
                         cudaFuncAttributeMaxDynamicSharedMemorySize, ASMEM);

    float *xr, *wqkvr, *wprojr, *gy_ptr;
    cudaGetSymbolAddress((void**)&xr, g_xr);
    cudaGetSymbolAddress((void**)&wqkvr, g_wqkvr);
    cudaGetSymbolAddress((void**)&wprojr, g_wprojr);
    cudaGetSymbolAddress((void**)&gy_ptr, g_y);

    init_tables<<<(TSEQ + UPAD + 255) / 256, 256>>>(cpar, lmul);

    // Pre-round GEMM inputs to tf32 (rna) — removes all mainloop cvt.
    const int nx = BSZ * TSEQ * CDIM / 4;
    const int nq = CDIM * 3 * CDIM / 4;
    const int np = CDIM * CDIM / 4;
    cvt_tf32<<<(nx + 255) / 256, 256>>>((const float4*)x, (float4*)xr, nx);
    cvt_tf32<<<(nq + 255) / 256, 256>>>((const float4*)Wqkv, (float4*)wqkvr, nq);
    cvt_tf32<<<(np + 255) / 256, 256>>>((const float4*)Wproj, (float4*)wprojr, np);

    mma_gemm<0><<<dim3(3 * CDIM / 128, BSZ * TSEQ / 128), 256, GSMEM>>>(
        xr, wqkvr, bqkv, nullptr, CDIM, 3 * CDIM);

    attn_mma<<<dim3(TSEQ / 128, NH, BSZ), 256, ASMEM>>>(w1, b1, w2);

    mma_gemm<1><<<dim3(CDIM / 128, BSZ * TSEQ / 128), 256, GSMEM>>>(
        gy_ptr, wprojr, bproj, out, CDIM, CDIM);
}